// round 14
// baseline (speedup 1.0000x reference)
#include <cuda_runtime.h>
#include <cuda_fp16.h>
#include <math.h>
#include <stdint.h>

#define ALPHA 0.2f

static constexpr int Bb = 8;     // batch
static constexpr int Nn = 2048;  // nodes
static constexpr int Ff = 256;   // features (Fin == Fout)

// ---------------------------------------------------------------------------
// Scratch (__device__ globals: allocation-free rule)
// ---------------------------------------------------------------------------
__device__ __align__(1024) __half g_hf[(size_t)Bb * Nn * Ff];     // h as fp16
__device__ __align__(1024) __half g_wt[Ff * Ff];                  // W^T fp16
__device__ __align__(1024) __half g_wht[(size_t)Bb * Ff * Nn];    // WhT fp16
__device__ __align__(1024) __half g_at[(size_t)Bb * Nn * Nn];     // attn fp16 (67 MB)
__device__ __align__(16)   float g_s1[Bb * Nn];
__device__ __align__(16)   float g_s2[Bb * Nn];
__device__ __align__(16)   float g_wa[2 * Ff];

// ---------------------------------------------------------------------------
// Helpers (baseline PTX only: mma.sync / ldmatrix / cp.async)
// ---------------------------------------------------------------------------
__device__ __forceinline__ uint32_t smem_u32(const void* p) {
    uint32_t a;
    asm("{ .reg .u64 t; cvta.to.shared.u64 t, %1; cvt.u32.u64 %0, t; }" : "=r"(a) : "l"(p));
    return a;
}
#define LDSM4(r0, r1, r2, r3, addr) \
    asm volatile("ldmatrix.sync.aligned.m8n8.x4.shared.b16 {%0,%1,%2,%3}, [%4];" \
                 : "=r"(r0), "=r"(r1), "=r"(r2), "=r"(r3) : "r"(addr))
#define MMA16816(d, a, b) \
    asm volatile("mma.sync.aligned.m16n8k16.row.col.f32.f16.f16.f32 " \
                 "{%0,%1,%2,%3},{%4,%5,%6,%7},{%8,%9},{%0,%1,%2,%3};" \
                 : "+f"((d)[0]), "+f"((d)[1]), "+f"((d)[2]), "+f"((d)[3]) \
                 : "r"((a)[0]), "r"((a)[1]), "r"((a)[2]), "r"((a)[3]), \
                   "r"((b)[0]), "r"((b)[1]))
#define CPA16(s, g) asm volatile("cp.async.cg.shared.global [%0], [%1], 16;" :: "r"(s), "l"(g))
#define CPCOMMIT()  asm volatile("cp.async.commit_group;" ::: "memory")
#define CPWAIT(n)   asm volatile("cp.async.wait_group %0;" :: "n"(n) : "memory")

__device__ __forceinline__ unsigned packh2(__half a, __half b) {
    __half2 t(a, b);
    return *reinterpret_cast<unsigned*>(&t);
}

// ---------------------------------------------------------------------------
// fp16 GEMM: C[M,Ntot] = A[M,K] @ B[Ntot,K]^T (both K-major)
// CTA 128x128, 8 warps (4m x 2n), warp tile 32x64, BK=64, 3-stage cp.async,
// one __syncthreads per K-iter, and DOUBLE-BUFFERED REGISTER FRAGMENTS:
// frags(ks+1) are loaded before the MMAs of ks, so LDSM latency overlaps the
// MMA issue burst instead of serializing with it.
// 2 CTAs/SM.  grid = (Ntot/128, M/128, batch).  EPI=0: fp32 C. EPI=1: fp16 Ch.
// ---------------------------------------------------------------------------
static constexpr int TSK    = 72;                 // padded row stride (fp16) for BK=64
static constexpr int TILE_K = 128 * TSK * 2;      // 18432 per 128-row tile
static constexpr int STAGE  = 2 * TILE_K;         // 36864 (A + B)
static constexpr int SMEM_G = 3 * STAGE;          // 110592

template<int EPI>
__global__ __launch_bounds__(256, 2) void k_mma_gemm(
    const __half* __restrict__ A0, const __half* __restrict__ B0,
    float* __restrict__ C, __half* __restrict__ Ch,
    int Ntot, int K, size_t sA, size_t sB, size_t sC)
{
    extern __shared__ __align__(128) char smem[];
    const int tid = threadIdx.x;
    const int wid = tid >> 5, lane = tid & 31;
    const int wm = (wid & 3) * 32;        // 4 m-warps
    const int wn = (wid >> 2) * 64;       // 2 n-warps
    const size_t bz = blockIdx.z;
    A0 += bz * sA;
    B0 += bz * sB;
    const int m0 = blockIdx.y * 128, n0 = blockIdx.x * 128;
    const uint32_t sb = smem_u32(smem);

    float acc[2][8][4];
    #pragma unroll
    for (int i = 0; i < 2; i++)
        #pragma unroll
        for (int j = 0; j < 8; j++)
            #pragma unroll
            for (int c = 0; c < 4; c++) acc[i][j][c] = 0.f;

    // loaders: each tile 128 rows x 8 chunks(16B) = 1024 chunks; 4/thread/tile
    auto issue = [&](int it, int buf) {
        const int k0 = it << 6;
        const uint32_t s = sb + buf * STAGE;
        #pragma unroll
        for (int r = 0; r < 4; r++) {
            int u = tid + r * 256;              // 0..1023
            int row = u >> 3, c = (u & 7) * 8;  // c in halves
            const uint32_t so = (uint32_t)(row * TSK + c) * 2;
            CPA16(s + so,          A0 + (size_t)(m0 + row) * K + k0 + c);
            CPA16(s + TILE_K + so, B0 + (size_t)(n0 + row) * K + k0 + c);
        }
    };

    const int l7 = lane & 7, lb3 = (lane >> 3) & 1, lb4 = lane >> 4;
    // precomputed ldmatrix row bases (constant across iterations)
    const uint32_t aBase = (uint32_t)((wm + l7 + lb3 * 8) * TSK + lb4 * 8) * 2;
    const uint32_t bBase = (uint32_t)(TILE_K) + (uint32_t)((wn + l7 + lb4 * 8) * TSK + lb3 * 8) * 2;
    const int nch = K >> 6;

    uint32_t af[2][2][4], bf[2][8][2];

    // fragment loader for ks-step within stage base s, into buffer pb
    auto ldfrags = [&](uint32_t s, int ks, int pb) {
        const uint32_t ko = (uint32_t)(ks * 16) * 2;   // byte offset in K
        #pragma unroll
        for (int mf = 0; mf < 2; mf++)
            LDSM4(af[pb][mf][0], af[pb][mf][1], af[pb][mf][2], af[pb][mf][3],
                  s + aBase + ko + (uint32_t)(mf * 16 * TSK) * 2);
        #pragma unroll
        for (int nq = 0; nq < 4; nq++)
            LDSM4(bf[pb][nq * 2][0], bf[pb][nq * 2][1],
                  bf[pb][nq * 2 + 1][0], bf[pb][nq * 2 + 1][1],
                  s + bBase + ko + (uint32_t)(nq * 16 * TSK) * 2);
    };

    issue(0, 0); CPCOMMIT();
    if (nch > 1) { issue(1, 1); CPCOMMIT(); }

    for (int i = 0; i < nch; i++) {
        if (i + 1 < nch) { CPWAIT(1); }   // stage i landed (only i+1 may be pending)
        else             { CPWAIT(0); }
        __syncthreads();                  // all warps done with MMA of i-1
        if (i + 2 < nch) { issue(i + 2, (i + 2) % 3); CPCOMMIT(); }

        const uint32_t s = sb + (i % 3) * STAGE;
        ldfrags(s, 0, 0);
        #pragma unroll
        for (int ks = 0; ks < 4; ks++) {
            const int cur = ks & 1;
            if (ks < 3) ldfrags(s, ks + 1, cur ^ 1);   // prefetch next frags
            #pragma unroll
            for (int mf = 0; mf < 2; mf++)
                #pragma unroll
                for (int nf = 0; nf < 8; nf++)
                    MMA16816(acc[mf][nf], af[cur][mf], bf[cur][nf]);
        }
    }

    const int crow = m0 + wm + (lane >> 2);
    const int ccol = n0 + wn + (lane & 3) * 2;
    if (EPI == 0) {
        float* Cb = C + bz * sC;
        #pragma unroll
        for (int mf = 0; mf < 2; mf++)
            #pragma unroll
            for (int nf = 0; nf < 8; nf++) {
                float* p0 = Cb + (size_t)(crow + mf * 16)     * Ntot + ccol + nf * 8;
                float* p1 = Cb + (size_t)(crow + mf * 16 + 8) * Ntot + ccol + nf * 8;
                *(float2*)p0 = make_float2(acc[mf][nf][0], acc[mf][nf][1]);
                *(float2*)p1 = make_float2(acc[mf][nf][2], acc[mf][nf][3]);
            }
    } else {
        __half* Hb = Ch + bz * sC;
        #pragma unroll
        for (int mf = 0; mf < 2; mf++)
            #pragma unroll
            for (int nf = 0; nf < 8; nf++) {
                const size_t o0 = (size_t)(crow + mf * 16)     * Ntot + ccol + nf * 8;
                const size_t o1 = (size_t)(crow + mf * 16 + 8) * Ntot + ccol + nf * 8;
                *(unsigned*)(Hb + o0) = packh2(__float2half_rn(acc[mf][nf][0]),
                                               __float2half_rn(acc[mf][nf][1]));
                *(unsigned*)(Hb + o1) = packh2(__float2half_rn(acc[mf][nf][2]),
                                               __float2half_rn(acc[mf][nf][3]));
            }
    }
}

// ---------------------------------------------------------------------------
// Prep W: Wt fp16 (block o transposes col o); block 0 also computes wa1/wa2.
// ---------------------------------------------------------------------------
__global__ void k_prep_w(const float* __restrict__ W, const float* __restrict__ a,
                         __half* __restrict__ T) {
    const int o = blockIdx.x, f = threadIdx.x;
    T[(size_t)o * Ff + f] = __float2half_rn(W[(size_t)f * Ff + o]);
    if (o == 0) {
        float d1 = 0.f, d2 = 0.f;
        const float* wrow = W + (size_t)f * Ff;
        #pragma unroll 8
        for (int j = 0; j < Ff; j++) {
            float w = wrow[j];
            d1 += w * a[j];
            d2 += w * a[Ff + j];
        }
        g_wa[f] = d1;
        g_wa[Ff + f] = d2;
    }
}

// ---------------------------------------------------------------------------
// Prep h: fp16 conversion + s1/s2 dots (reads h exactly once). Warp per row.
// ---------------------------------------------------------------------------
__global__ __launch_bounds__(256) void k_prep_h(const float* __restrict__ h,
                                                __half* __restrict__ hf) {
    __shared__ float swa[2 * Ff];
    for (int i = threadIdx.x; i < 2 * Ff; i += 256) swa[i] = g_wa[i];
    __syncthreads();

    const int warp = threadIdx.x >> 5, lane = threadIdx.x & 31;
    const int row = blockIdx.x * 8 + warp;
    const float* hp = h + (size_t)row * Ff;
    const int j0 = lane * 8;

    float4 v0 = *(const float4*)(hp + j0), v1 = *(const float4*)(hp + j0 + 4);
    float v[8] = {v0.x, v0.y, v0.z, v0.w, v1.x, v1.y, v1.z, v1.w};

    unsigned pk[4];
    #pragma unroll
    for (int k = 0; k < 4; k++)
        pk[k] = packh2(__float2half_rn(v[2 * k]), __float2half_rn(v[2 * k + 1]));
    *(uint4*)(hf + (size_t)row * Ff + j0) = make_uint4(pk[0], pk[1], pk[2], pk[3]);

    float d1 = 0.f, d2 = 0.f;
    #pragma unroll
    for (int k = 0; k < 8; k++) {
        d1 += v[k] * swa[j0 + k];
        d2 += v[k] * swa[Ff + j0 + k];
    }
    #pragma unroll
    for (int off = 16; off; off >>= 1) {
        d1 += __shfl_xor_sync(0xffffffffu, d1, off);
        d2 += __shfl_xor_sync(0xffffffffu, d2, off);
    }
    if (lane == 0) { g_s1[row] = d1; g_s2[row] = d2; }
}

// ---------------------------------------------------------------------------
// Attention softmax: one block per node i handles TWO batches (adj row loaded
// once, reused). adj is exactly {0,1}, so mask = multiply (no select).
// ---------------------------------------------------------------------------
__global__ __launch_bounds__(256) void k_attn(const float* __restrict__ adj,
                                              __half* __restrict__ At) {
    const int i = blockIdx.x;
    const int b0 = blockIdx.y * 2;
    const int tid = threadIdx.x;
    const int warp = tid >> 5, lane = tid & 31;
    const int j0 = tid * 8;
    __shared__ float sred[8 * 2];
    __shared__ float sinv[2];

    const float* ar = adj + (size_t)i * Nn;
    float4 a0 = *(const float4*)(ar + j0), a1 = *(const float4*)(ar + j0 + 4);
    float av[8] = {a0.x, a0.y, a0.z, a0.w, a1.x, a1.y, a1.z, a1.w};

    float p[2][8], lsum[2];
    #pragma unroll
    for (int q = 0; q < 2; q++) {
        const int b = b0 + q;
        const float s1i = g_s1[b * Nn + i];
        const float* s2p = g_s2 + b * Nn + j0;
        float4 q0 = *(const float4*)(s2p), q1 = *(const float4*)(s2p + 4);
        float sv[8] = {q0.x, q0.y, q0.z, q0.w, q1.x, q1.y, q1.z, q1.w};
        float ls = 0.f;
        #pragma unroll
        for (int k = 0; k < 8; k++) {
            float t = s1i + sv[k];
            t = (t >= 0.f) ? t : ALPHA * t;
            float pv = av[k] * __expf(t);   // adj in {0,1}: multiply == mask
            p[q][k] = pv;
            ls += pv;
        }
        lsum[q] = ls;
    }

    #pragma unroll
    for (int q = 0; q < 2; q++) {
        #pragma unroll
        for (int off = 16; off; off >>= 1)
            lsum[q] += __shfl_xor_sync(0xffffffffu, lsum[q], off);
    }
    if (lane == 0) { sred[warp * 2] = lsum[0]; sred[warp * 2 + 1] = lsum[1]; }
    __syncthreads();
    if (tid < 2) {
        float s = 0.f;
        #pragma unroll
        for (int w = 0; w < 8; w++) s += sred[w * 2 + tid];
        sinv[tid] = 1.f / s;
    }
    __syncthreads();

    #pragma unroll
    for (int q = 0; q < 2; q++) {
        const float inv = sinv[q];
        unsigned pk[4];
        #pragma unroll
        for (int k = 0; k < 4; k++)
            pk[k] = packh2(__float2half_rn(p[q][2 * k] * inv),
                           __float2half_rn(p[q][2 * k + 1] * inv));
        *(uint4*)(At + ((size_t)(b0 + q) * Nn + i) * Nn + j0) =
            make_uint4(pk[0], pk[1], pk[2], pk[3]);
    }
}

// ---------------------------------------------------------------------------
// Launch
// ---------------------------------------------------------------------------
extern "C" void kernel_launch(void* const* d_in, const int* in_sizes, int n_in,
                              void* d_out, int out_size) {
    const float* h   = (const float*)d_in[0];  // [8, 2048, 256]
    const float* adj = (const float*)d_in[1];  // [2048, 2048]
    const float* W   = (const float*)d_in[2];  // [256, 256]
    const float* a   = (const float*)d_in[3];  // [512, 1]
    float* out = (float*)d_out;                // [8, 2048, 256]

    __half *hf, *wt, *wht, *at;
    cudaGetSymbolAddress((void**)&hf,  g_hf);
    cudaGetSymbolAddress((void**)&wt,  g_wt);
    cudaGetSymbolAddress((void**)&wht, g_wht);
    cudaGetSymbolAddress((void**)&at,  g_at);

    cudaFuncSetAttribute(k_mma_gemm<0>, cudaFuncAttributeMaxDynamicSharedMemorySize, SMEM_G);
    cudaFuncSetAttribute(k_mma_gemm<1>, cudaFuncAttributeMaxDynamicSharedMemorySize, SMEM_G);

    k_prep_w<<<Ff, Ff>>>(W, a, wt);
    k_prep_h<<<(Bb * Nn) / 8, 256>>>(h, hf);

    // GEMM1 (fused transpose): WhT[b][o][n] = sum_f Wt[o,f] * h[b,n,f]
    //   A = Wt (M=256, K=256), B = h[b] (Ntot=2048, K=256)
    k_mma_gemm<1><<<dim3(Nn / 128, Ff / 128, Bb), 256, SMEM_G>>>(
        wt, hf, nullptr, wht, Nn, Ff, 0, (size_t)Nn * Ff, (size_t)Ff * Nn);

    // softmax rows -> attn fp16 (one block per node, 2 batches each)
    k_attn<<<dim3(Nn, Bb / 2), 256>>>(adj, at);

    // GEMM2: out[b][i][o] = sum_k P[b][i][k] * WhT[b][o][k]
    //   A = P (M=2048, K=2048), B = WhT (Ntot=256, K=2048)
    k_mma_gemm<0><<<dim3(Ff / 128, Nn / 128, Bb), 256, SMEM_G>>>(
        at, wht, out, nullptr, Ff, Nn,
        (size_t)Nn * Nn, (size_t)Ff * Nn, (size_t)Nn * Ff);
}

// round 15
// speedup vs baseline: 1.0225x; 1.0225x over previous
#include <cuda_runtime.h>
#include <cuda_fp16.h>
#include <math.h>
#include <stdint.h>

#define ALPHA 0.2f

static constexpr int Bb = 8;     // batch
static constexpr int Nn = 2048;  // nodes
static constexpr int Ff = 256;   // features (Fin == Fout)

// ---------------------------------------------------------------------------
// Scratch (__device__ globals: allocation-free rule)
// ---------------------------------------------------------------------------
__device__ __align__(1024) __half g_hf[(size_t)Bb * Nn * Ff];     // h as fp16
__device__ __align__(1024) __half g_wt[Ff * Ff];                  // W^T fp16
__device__ __align__(1024) __half g_wht[(size_t)Bb * Ff * Nn];    // WhT fp16
__device__ __align__(1024) __half g_at[(size_t)Bb * Nn * Nn];     // attn fp16 (67 MB)
__device__ __align__(16)   float g_s1[Bb * Nn];
__device__ __align__(16)   float g_s2[Bb * Nn];
__device__ __align__(16)   float g_wa[2 * Ff];

// ---------------------------------------------------------------------------
// Helpers (baseline PTX only: mma.sync / ldmatrix / cp.async)
// ---------------------------------------------------------------------------
__device__ __forceinline__ uint32_t smem_u32(const void* p) {
    uint32_t a;
    asm("{ .reg .u64 t; cvta.to.shared.u64 t, %1; cvt.u32.u64 %0, t; }" : "=r"(a) : "l"(p));
    return a;
}
#define LDSM4(r0, r1, r2, r3, addr) \
    asm volatile("ldmatrix.sync.aligned.m8n8.x4.shared.b16 {%0,%1,%2,%3}, [%4];" \
                 : "=r"(r0), "=r"(r1), "=r"(r2), "=r"(r3) : "r"(addr))
#define MMA16816(d, a, b) \
    asm volatile("mma.sync.aligned.m16n8k16.row.col.f32.f16.f16.f32 " \
                 "{%0,%1,%2,%3},{%4,%5,%6,%7},{%8,%9},{%0,%1,%2,%3};" \
                 : "+f"((d)[0]), "+f"((d)[1]), "+f"((d)[2]), "+f"((d)[3]) \
                 : "r"((a)[0]), "r"((a)[1]), "r"((a)[2]), "r"((a)[3]), \
                   "r"((b)[0]), "r"((b)[1]))
#define CPA16(s, g) asm volatile("cp.async.cg.shared.global [%0], [%1], 16;" :: "r"(s), "l"(g))
#define CPCOMMIT()  asm volatile("cp.async.commit_group;" ::: "memory")
#define CPWAIT(n)   asm volatile("cp.async.wait_group %0;" :: "n"(n) : "memory")

__device__ __forceinline__ unsigned packh2(__half a, __half b) {
    __half2 t(a, b);
    return *reinterpret_cast<unsigned*>(&t);
}

// ---------------------------------------------------------------------------
// fp16 GEMM: C[M,Ntot] = A[M,K] @ B[Ntot,K]^T (both K-major)
// CTA 128x128, 8 warps (4m x 2n), warp tile 32x64, BK=64, 3-stage cp.async,
// one __syncthreads per K-iter. 2 CTAs/SM.
// grid = (Ntot/128, M/128, batch).  EPI=0: fp32 C. EPI=1: fp16 Ch.
// ---------------------------------------------------------------------------
static constexpr int TSK    = 72;                 // padded row stride (fp16) for BK=64
static constexpr int TILE_K = 128 * TSK * 2;      // 18432 per 128-row tile
static constexpr int STAGE  = 2 * TILE_K;         // 36864 (A + B)
static constexpr int SMEM_G = 3 * STAGE;          // 110592

template<int EPI>
__global__ __launch_bounds__(256, 2) void k_mma_gemm(
    const __half* __restrict__ A0, const __half* __restrict__ B0,
    float* __restrict__ C, __half* __restrict__ Ch,
    int Ntot, int K, size_t sA, size_t sB, size_t sC)
{
    extern __shared__ __align__(128) char smem[];
    const int tid = threadIdx.x;
    const int wid = tid >> 5, lane = tid & 31;
    const int wm = (wid & 3) * 32;        // 4 m-warps
    const int wn = (wid >> 2) * 64;       // 2 n-warps
    const size_t bz = blockIdx.z;
    A0 += bz * sA;
    B0 += bz * sB;
    const int m0 = blockIdx.y * 128, n0 = blockIdx.x * 128;
    const uint32_t sb = smem_u32(smem);

    float acc[2][8][4];
    #pragma unroll
    for (int i = 0; i < 2; i++)
        #pragma unroll
        for (int j = 0; j < 8; j++)
            #pragma unroll
            for (int c = 0; c < 4; c++) acc[i][j][c] = 0.f;

    // loaders: each tile 128 rows x 8 chunks(16B) = 1024 chunks; 4/thread/tile
    auto issue = [&](int it, int buf) {
        const int k0 = it << 6;
        const uint32_t s = sb + buf * STAGE;
        #pragma unroll
        for (int r = 0; r < 4; r++) {
            int u = tid + r * 256;              // 0..1023
            int row = u >> 3, c = (u & 7) * 8;  // c in halves
            const uint32_t so = (uint32_t)(row * TSK + c) * 2;
            CPA16(s + so,          A0 + (size_t)(m0 + row) * K + k0 + c);
            CPA16(s + TILE_K + so, B0 + (size_t)(n0 + row) * K + k0 + c);
        }
    };

    const int l7 = lane & 7, lb3 = (lane >> 3) & 1, lb4 = lane >> 4;
    const int nch = K >> 6;

    issue(0, 0); CPCOMMIT();
    if (nch > 1) { issue(1, 1); CPCOMMIT(); }

    for (int i = 0; i < nch; i++) {
        if (i + 1 < nch) { CPWAIT(1); }   // stage i landed
        else             { CPWAIT(0); }
        __syncthreads();                  // all warps done with MMA of i-1
        if (i + 2 < nch) { issue(i + 2, (i + 2) % 3); CPCOMMIT(); }

        const uint32_t s = sb + (i % 3) * STAGE;
        #pragma unroll
        for (int ks = 0; ks < 4; ks++) {
            const int ko = ks * 16;
            uint32_t af[2][4], bf[8][2];
            #pragma unroll
            for (int mf = 0; mf < 2; mf++) {
                int row = wm + mf * 16 + l7 + lb3 * 8;
                LDSM4(af[mf][0], af[mf][1], af[mf][2], af[mf][3],
                      s + (uint32_t)(row * TSK + ko + lb4 * 8) * 2);
            }
            #pragma unroll
            for (int nq = 0; nq < 4; nq++) {
                int nr = wn + nq * 16 + l7 + lb4 * 8;
                LDSM4(bf[nq * 2][0], bf[nq * 2][1], bf[nq * 2 + 1][0], bf[nq * 2 + 1][1],
                      s + TILE_K + (uint32_t)(nr * TSK + ko + lb3 * 8) * 2);
            }
            #pragma unroll
            for (int mf = 0; mf < 2; mf++)
                #pragma unroll
                for (int nf = 0; nf < 8; nf++) MMA16816(acc[mf][nf], af[mf], bf[nf]);
        }
    }

    const int crow = m0 + wm + (lane >> 2);
    const int ccol = n0 + wn + (lane & 3) * 2;
    if (EPI == 0) {
        float* Cb = C + bz * sC;
        #pragma unroll
        for (int mf = 0; mf < 2; mf++)
            #pragma unroll
            for (int nf = 0; nf < 8; nf++) {
                float* p0 = Cb + (size_t)(crow + mf * 16)     * Ntot + ccol + nf * 8;
                float* p1 = Cb + (size_t)(crow + mf * 16 + 8) * Ntot + ccol + nf * 8;
                *(float2*)p0 = make_float2(acc[mf][nf][0], acc[mf][nf][1]);
                *(float2*)p1 = make_float2(acc[mf][nf][2], acc[mf][nf][3]);
            }
    } else {
        __half* Hb = Ch + bz * sC;
        #pragma unroll
        for (int mf = 0; mf < 2; mf++)
            #pragma unroll
            for (int nf = 0; nf < 8; nf++) {
                const size_t o0 = (size_t)(crow + mf * 16)     * Ntot + ccol + nf * 8;
                const size_t o1 = (size_t)(crow + mf * 16 + 8) * Ntot + ccol + nf * 8;
                *(unsigned*)(Hb + o0) = packh2(__float2half_rn(acc[mf][nf][0]),
                                               __float2half_rn(acc[mf][nf][1]));
                *(unsigned*)(Hb + o1) = packh2(__float2half_rn(acc[mf][nf][2]),
                                               __float2half_rn(acc[mf][nf][3]));
            }
    }
}

// ---------------------------------------------------------------------------
// Prep W: Wt fp16 (block o transposes col o); block 0 also computes wa1/wa2.
// ---------------------------------------------------------------------------
__global__ void k_prep_w(const float* __restrict__ W, const float* __restrict__ a,
                         __half* __restrict__ T) {
    const int o = blockIdx.x, f = threadIdx.x;
    T[(size_t)o * Ff + f] = __float2half_rn(W[(size_t)f * Ff + o]);
    if (o == 0) {
        float d1 = 0.f, d2 = 0.f;
        const float* wrow = W + (size_t)f * Ff;
        #pragma unroll 8
        for (int j = 0; j < Ff; j++) {
            float w = wrow[j];
            d1 += w * a[j];
            d2 += w * a[Ff + j];
        }
        g_wa[f] = d1;
        g_wa[Ff + f] = d2;
    }
}

// ---------------------------------------------------------------------------
// Prep h: fp16 conversion + s1/s2 dots (reads h exactly once). Warp per row.
// ---------------------------------------------------------------------------
__global__ __launch_bounds__(256) void k_prep_h(const float* __restrict__ h,
                                                __half* __restrict__ hf) {
    __shared__ float swa[2 * Ff];
    for (int i = threadIdx.x; i < 2 * Ff; i += 256) swa[i] = g_wa[i];
    __syncthreads();

    const int warp = threadIdx.x >> 5, lane = threadIdx.x & 31;
    const int row = blockIdx.x * 8 + warp;
    const float* hp = h + (size_t)row * Ff;
    const int j0 = lane * 8;

    float4 v0 = *(const float4*)(hp + j0), v1 = *(const float4*)(hp + j0 + 4);
    float v[8] = {v0.x, v0.y, v0.z, v0.w, v1.x, v1.y, v1.z, v1.w};

    unsigned pk[4];
    #pragma unroll
    for (int k = 0; k < 4; k++)
        pk[k] = packh2(__float2half_rn(v[2 * k]), __float2half_rn(v[2 * k + 1]));
    *(uint4*)(hf + (size_t)row * Ff + j0) = make_uint4(pk[0], pk[1], pk[2], pk[3]);

    float d1 = 0.f, d2 = 0.f;
    #pragma unroll
    for (int k = 0; k < 8; k++) {
        d1 += v[k] * swa[j0 + k];
        d2 += v[k] * swa[Ff + j0 + k];
    }
    #pragma unroll
    for (int off = 16; off; off >>= 1) {
        d1 += __shfl_xor_sync(0xffffffffu, d1, off);
        d2 += __shfl_xor_sync(0xffffffffu, d2, off);
    }
    if (lane == 0) { g_s1[row] = d1; g_s2[row] = d2; }
}

// ---------------------------------------------------------------------------
// Attention softmax: one block per node i handles FOUR batches (adj row
// loaded once, reused 4x). ~50 regs -> occupancy stays high. grid (Nn, 2).
// adj is exactly {0,1}, so mask = multiply.
// ---------------------------------------------------------------------------
__global__ __launch_bounds__(256) void k_attn(const float* __restrict__ adj,
                                              __half* __restrict__ At) {
    const int i = blockIdx.x;
    const int b0 = blockIdx.y * 4;
    const int tid = threadIdx.x;
    const int warp = tid >> 5, lane = tid & 31;
    const int j0 = tid * 8;
    __shared__ float sred[8 * 4];
    __shared__ float sinv[4];

    const float* ar = adj + (size_t)i * Nn;
    float4 a0 = *(const float4*)(ar + j0), a1 = *(const float4*)(ar + j0 + 4);
    float av[8] = {a0.x, a0.y, a0.z, a0.w, a1.x, a1.y, a1.z, a1.w};

    float p[4][8], lsum[4];
    #pragma unroll
    for (int q = 0; q < 4; q++) {
        const int b = b0 + q;
        const float s1i = g_s1[b * Nn + i];
        const float* s2p = g_s2 + b * Nn + j0;
        float4 q0 = *(const float4*)(s2p), q1 = *(const float4*)(s2p + 4);
        float sv[8] = {q0.x, q0.y, q0.z, q0.w, q1.x, q1.y, q1.z, q1.w};
        float ls = 0.f;
        #pragma unroll
        for (int k = 0; k < 8; k++) {
            float t = s1i + sv[k];
            t = (t >= 0.f) ? t : ALPHA * t;
            float pv = av[k] * __expf(t);
            p[q][k] = pv;
            ls += pv;
        }
        lsum[q] = ls;
    }

    #pragma unroll
    for (int q = 0; q < 4; q++) {
        #pragma unroll
        for (int off = 16; off; off >>= 1)
            lsum[q] += __shfl_xor_sync(0xffffffffu, lsum[q], off);
    }
    if (lane == 0) {
        #pragma unroll
        for (int q = 0; q < 4; q++) sred[warp * 4 + q] = lsum[q];
    }
    __syncthreads();
    if (tid < 4) {
        float s = 0.f;
        #pragma unroll
        for (int w = 0; w < 8; w++) s += sred[w * 4 + tid];
        sinv[tid] = 1.f / s;
    }
    __syncthreads();

    #pragma unroll
    for (int q = 0; q < 4; q++) {
        const float inv = sinv[q];
        unsigned pk[4];
        #pragma unroll
        for (int k = 0; k < 4; k++)
            pk[k] = packh2(__float2half_rn(p[q][2 * k] * inv),
                           __float2half_rn(p[q][2 * k + 1] * inv));
        *(uint4*)(At + ((size_t)(b0 + q) * Nn + i) * Nn + j0) =
            make_uint4(pk[0], pk[1], pk[2], pk[3]);
    }
}

// ---------------------------------------------------------------------------
// Launch: fork k_attn onto a side stream so it overlaps GEMM1.
// Streams/events are created once on the FIRST (uncaptured) call; during
// graph capture only launches + event record/wait occur (capturable).
// ---------------------------------------------------------------------------
extern "C" void kernel_launch(void* const* d_in, const int* in_sizes, int n_in,
                              void* d_out, int out_size) {
    const float* h   = (const float*)d_in[0];  // [8, 2048, 256]
    const float* adj = (const float*)d_in[1];  // [2048, 2048]
    const float* W   = (const float*)d_in[2];  // [256, 256]
    const float* a   = (const float*)d_in[3];  // [512, 1]
    float* out = (float*)d_out;                // [8, 2048, 256]

    __half *hf, *wt, *wht, *at;
    cudaGetSymbolAddress((void**)&hf,  g_hf);
    cudaGetSymbolAddress((void**)&wt,  g_wt);
    cudaGetSymbolAddress((void**)&wht, g_wht);
    cudaGetSymbolAddress((void**)&at,  g_at);

    static cudaStream_t sAux = nullptr;
    static cudaEvent_t eFork = nullptr, eJoin = nullptr;
    if (!sAux) {
        cudaStreamCreateWithFlags(&sAux, cudaStreamNonBlocking);
        cudaEventCreateWithFlags(&eFork, cudaEventDisableTiming);
        cudaEventCreateWithFlags(&eJoin, cudaEventDisableTiming);
        cudaFuncSetAttribute(k_mma_gemm<0>, cudaFuncAttributeMaxDynamicSharedMemorySize, SMEM_G);
        cudaFuncSetAttribute(k_mma_gemm<1>, cudaFuncAttributeMaxDynamicSharedMemorySize, SMEM_G);
    }

    k_prep_w<<<Ff, Ff>>>(W, a, wt);
    k_prep_h<<<(Bb * Nn) / 8, 256>>>(h, hf);

    // fork: k_attn (needs s1/s2 from prep_h) runs on sAux, overlapping GEMM1
    cudaEventRecord(eFork, 0);
    cudaStreamWaitEvent(sAux, eFork, 0);
    k_attn<<<dim3(Nn, Bb / 4), 256, 0, sAux>>>(adj, at);

    // GEMM1 (fused transpose): WhT[b][o][n] = sum_f Wt[o,f] * h[b,n,f]
    k_mma_gemm<1><<<dim3(Nn / 128, Ff / 128, Bb), 256, SMEM_G>>>(
        wt, hf, nullptr, wht, Nn, Ff, 0, (size_t)Nn * Ff, (size_t)Ff * Nn);

    // join: GEMM2 needs both attn (sAux) and WhT (main)
    cudaEventRecord(eJoin, sAux);
    cudaStreamWaitEvent(0, eJoin, 0);

    // GEMM2: out[b][i][o] = sum_k P[b][i][k] * WhT[b][o][k]
    k_mma_gemm<0><<<dim3(Ff / 128, Nn / 128, Bb), 256, SMEM_G>>>(
        at, wht, out, nullptr, Ff, Nn,
        (size_t)Nn * Nn, (size_t)Ff * Nn, (size_t)Nn * Ff);
}